// round 17
// baseline (speedup 1.0000x reference)
#include <cuda_runtime.h>
#include <cuda_fp16.h>
#include <cstdint>

// Problem constants
#define B_DIM 16384
#define I_DIM 512
#define H1D   256
#define H2D   128
#define E_DIM 8
#define T_DIM 2

// ---------------------------------------------------------------------------
// Device globals — single-fp16 numerics for both operands (1 MMA / product).
// Measured calibration: rel_err 3.27e-4 vs 1e-3 threshold (R16).
// ---------------------------------------------------------------------------
__device__ __half g_x16[(size_t)B_DIM * I_DIM];
__device__ __half g_w1t[(size_t)E_DIM * H1D * I_DIM];   // [E][H1][I]
__device__ __half g_w2t[(size_t)E_DIM * H2D * H1D];     // [E][H2][H1]
__device__ __half g_wgt[16 * I_DIM];                    // [t*8+e][I]
__device__ __half g_h16[(size_t)E_DIM * B_DIM * H1D];   // [E][B][H1]
__device__ float  g_glogits[(size_t)B_DIM * 16];        // [B][t*8+e]

// ---------------------------------------------------------------------------
// Helpers (sm_80+ only — environment compiles virtual compute_103, which
// rejects all tcgen05/sm_103a-suffix instructions)
// ---------------------------------------------------------------------------
__device__ __forceinline__ uint32_t smem_u32(const void* p) {
    uint32_t a;
    asm("{ .reg .u64 t; cvta.to.shared.u64 t, %1; cvt.u32.u64 %0, t; }"
        : "=r"(a) : "l"(p));
    return a;
}

// 128B-period XOR swizzle
#define SWZ(o) ((uint32_t)(o) ^ ((((uint32_t)(o)) >> 3) & 0x70u))

__device__ __forceinline__ void cp16(uint32_t s, const void* g) {
    asm volatile("cp.async.cg.shared.global [%0], [%1], 16;"
                 :: "r"(s), "l"(__cvta_generic_to_global(g)));
}
#define CP_COMMIT() asm volatile("cp.async.commit_group;" ::: "memory")
#define CP_WAIT1()  asm volatile("cp.async.wait_group 1;" ::: "memory")
#define CP_WAIT2()  asm volatile("cp.async.wait_group 2;" ::: "memory")

__device__ __forceinline__ void ldsm4(uint32_t* r, uint32_t addr) {
    asm volatile("ldmatrix.sync.aligned.m8n8.x4.shared.b16 {%0,%1,%2,%3}, [%4];"
                 : "=r"(r[0]), "=r"(r[1]), "=r"(r[2]), "=r"(r[3]) : "r"(addr));
}

__device__ __forceinline__ void mma16816(float* d, const uint32_t* a, const uint32_t* b) {
    asm volatile("mma.sync.aligned.m16n8k16.row.col.f32.f16.f16.f32 "
                 "{%0,%1,%2,%3}, {%4,%5,%6,%7}, {%8,%9}, {%0,%1,%2,%3};"
                 : "+f"(d[0]), "+f"(d[1]), "+f"(d[2]), "+f"(d[3])
                 : "r"(a[0]), "r"(a[1]), "r"(a[2]), "r"(a[3]), "r"(b[0]), "r"(b[1]));
}

// ---------------------------------------------------------------------------
// GEMM1 stage layout (34816 B):  A @0 (16K) | B @16K (16K) | Wg @32K (2K)
// 3 stages (104448 B) -> 2 CTAs/SM.  Always-commit, wait_group 1.
// Warp grid: 8 warps = 4(m) x 2(n); warp tile 32x64 = 2x8 m16n8 tiles.
// ---------------------------------------------------------------------------
#define G1_STAGE 34816
#define G1_SMEM  (3 * G1_STAGE)

__device__ __forceinline__ void gemm1_compute(uint32_t sb, int wm, int wn, int L,
                                              float acc[2][8][4],
                                              bool gate, float gacc[2][2][4]) {
#pragma unroll
    for (int ks = 0; ks < 4; ks++) {
        uint32_t af[2][4], bf[8][2];
#pragma unroll
        for (int mt = 0; mt < 2; mt++) {
            int row = wm + mt * 16 + (L & 15);
            int co = ks * 32 + ((L >> 4) & 1) * 16;
            ldsm4(af[mt], sb + 0u + SWZ(row * 128 + co));
        }
#pragma unroll
        for (int np = 0; np < 4; np++) {
            int g = L >> 3;
            int n = wn + np * 16 + (g >> 1) * 8 + (L & 7);
            int co = ks * 32 + (g & 1) * 16;
            uint32_t r[4];
            ldsm4(r, sb + 16384u + SWZ(n * 128 + co));
            bf[np * 2][0] = r[0]; bf[np * 2][1] = r[1];
            bf[np * 2 + 1][0] = r[2]; bf[np * 2 + 1][1] = r[3];
        }
#pragma unroll
        for (int mt = 0; mt < 2; mt++)
#pragma unroll
            for (int nt = 0; nt < 8; nt++)
                mma16816(acc[mt][nt], af[mt], bf[nt]);
        if (gate) {
            int g = L >> 3;
            int n = (g >> 1) * 8 + (L & 7);
            int co = ks * 32 + (g & 1) * 16;
            uint32_t rg[4];
            ldsm4(rg, sb + 32768u + SWZ(n * 128 + co));
            uint32_t gb[2][2] = {{rg[0], rg[1]}, {rg[2], rg[3]}};
#pragma unroll
            for (int mt = 0; mt < 2; mt++)
#pragma unroll
                for (int gt = 0; gt < 2; gt++)
                    mma16816(gacc[mt][gt], af[mt], gb[gt]);
        }
    }
}

__device__ __forceinline__ void gemm1_load(uint32_t smb, int stage, int tid, int k0,
                                           const __half* Aw, const __half* Bw,
                                           bool gate) {
    uint32_t sb = smb + (uint32_t)stage * G1_STAGE;
#pragma unroll
    for (int t = 0; t < 8; t++) {
        const int mat = t >> 2;   // 0: A, 1: B
        const __half* p = (mat == 0) ? Aw : Bw;
        int j = (t & 3) * 256 + tid;
        int row = j >> 3, c8 = j & 7;
        cp16(sb + (uint32_t)mat * 16384u + SWZ(row * 128 + c8 * 16),
             p + (size_t)row * I_DIM + k0 + c8 * 8);
    }
    if (gate && tid < 128) {
        int row = tid >> 3, c8 = tid & 7;
        cp16(sb + 32768u + SWZ(row * 128 + c8 * 16),
             g_wgt + (size_t)row * I_DIM + k0 + c8 * 8);
    }
    CP_COMMIT();
}

// ---------------------------------------------------------------------------
// GEMM1: C[b][h1] = x[b][:] . w1t[h1][:]  (per expert), +b1, relu -> g_h16.
// Gate CTAs (n0==0,e==0) also emit x@Wg^T logits.
// grid = (B/128, H1/128, E), 256 threads, 2 CTAs/SM.
// ---------------------------------------------------------------------------
__global__ void __launch_bounds__(256, 2)
gemm1_kernel(const float* __restrict__ b1) {
    extern __shared__ char sm[];
    uint32_t smb = smem_u32(sm);
    const int e = blockIdx.z, b0 = blockIdx.x * 128, n0 = blockIdx.y * 128;
    const int tid = threadIdx.x, L = tid & 31, w = tid >> 5;
    const int wm = (w >> 1) * 32, wn = (w & 1) * 64;
    const bool gate = (blockIdx.y == 0) && (blockIdx.z == 0);

    const __half* Aw = g_x16 + (size_t)b0 * I_DIM;
    const __half* Bw = g_w1t + ((size_t)e * H1D + n0) * I_DIM;

    float acc[2][8][4];
    float gacc[2][2][4];
#pragma unroll
    for (int mt = 0; mt < 2; mt++) {
#pragma unroll
        for (int nt = 0; nt < 8; nt++)
#pragma unroll
            for (int q = 0; q < 4; q++) acc[mt][nt][q] = 0.f;
#pragma unroll
        for (int gt = 0; gt < 2; gt++)
#pragma unroll
            for (int q = 0; q < 4; q++) gacc[mt][gt][q] = 0.f;
    }

    // Prologue: prefetch chunks 0,1 into stages 0,1.
    gemm1_load(smb, 0, tid, 0, Aw, Bw, gate);
    gemm1_load(smb, 1, tid, 64, Aw, Bw, gate);

    // Mainloop: 3-stage rotation, always-commit, wait_group 1.
#pragma unroll
    for (int c = 0; c < 8; c++) {
        CP_WAIT1();
        __syncthreads();
        if (c + 2 < 8)
            gemm1_load(smb, (c + 2) % 3, tid, (c + 2) * 64, Aw, Bw, gate);
        else
            CP_COMMIT();
        gemm1_compute(smb + (uint32_t)(c % 3) * G1_STAGE, wm, wn, L, acc, gate, gacc);
    }

    // Epilogue: bias + relu -> fp16 h
    float bias[8][2];
#pragma unroll
    for (int nt = 0; nt < 8; nt++) {
        int gn = n0 + wn + nt * 8 + 2 * (L & 3);
        bias[nt][0] = b1[e * H1D + gn];
        bias[nt][1] = b1[e * H1D + gn + 1];
    }
#pragma unroll
    for (int mt = 0; mt < 2; mt++) {
        int gb = b0 + wm + mt * 16 + (L >> 2);
#pragma unroll
        for (int nt = 0; nt < 8; nt++) {
            int gn = n0 + wn + nt * 8 + 2 * (L & 3);
            float v00 = fmaxf(acc[mt][nt][0] + bias[nt][0], 0.f);
            float v01 = fmaxf(acc[mt][nt][1] + bias[nt][1], 0.f);
            float v10 = fmaxf(acc[mt][nt][2] + bias[nt][0], 0.f);
            float v11 = fmaxf(acc[mt][nt][3] + bias[nt][1], 0.f);
            size_t o0 = ((size_t)e * B_DIM + gb) * H1D + gn;
            size_t o1 = o0 + (size_t)8 * H1D;
            __half2 p0; p0.x = __float2half_rn(v00); p0.y = __float2half_rn(v01);
            __half2 p1; p1.x = __float2half_rn(v10); p1.y = __float2half_rn(v11);
            *(__half2*)(g_h16 + o0) = p0;
            *(__half2*)(g_h16 + o1) = p1;
        }
    }
    if (gate) {
#pragma unroll
        for (int mt = 0; mt < 2; mt++) {
            int gb = b0 + wm + mt * 16 + (L >> 2);
#pragma unroll
            for (int gt = 0; gt < 2; gt++) {
                int gc = gt * 8 + 2 * (L & 3);
                *(float2*)(g_glogits + (size_t)gb * 16 + gc) =
                    make_float2(gacc[mt][gt][0], gacc[mt][gt][1]);
                *(float2*)(g_glogits + (size_t)(gb + 8) * 16 + gc) =
                    make_float2(gacc[mt][gt][2], gacc[mt][gt][3]);
            }
        }
    }
}

// ---------------------------------------------------------------------------
// GEMM2 fused with softmax + gated combine.
// CTA: 64 b-rows x 128 h2-cols; loops over all 8 experts (32 K-chunks),
// accumulating out[t][b][:] += softmax_e(logits)[t][b][e] * relu(h@w2t + b2).
// Stage (24576 B): A @0 (8K) | B @8K (16K).  4 stages + 4K gate cache.
// 2 CTAs/SM -> all 256 CTAs resident in one wave.
// 8 warps = 2(m) x 4(n); warp tile 32x32.  grid = B/64, 256 threads.
// ---------------------------------------------------------------------------
#define G2_STAGE 24576
#define G2_SMEM  (4 * G2_STAGE + 4096)

__device__ __forceinline__ void gemm2_load(uint32_t smb, int stage, int tid,
                                           int b0, int cg) {
    int e = cg >> 2, k0 = (cg & 3) * 64;
    const __half* Aw = g_h16 + ((size_t)e * B_DIM + b0) * H1D;
    const __half* Bw = g_w2t + (size_t)e * H2D * H1D;
    uint32_t sb = smb + (uint32_t)stage * G2_STAGE;
#pragma unroll
    for (int t = 0; t < 6; t++) {
        int j = t * 256 + tid;
        const __half* p;
        uint32_t dst;
        int jj;
        if (j < 512) { jj = j;       p = Aw; dst = 0u; }
        else         { jj = j - 512; p = Bw; dst = 8192u; }
        int row = jj >> 3, c8 = jj & 7;
        cp16(sb + dst + SWZ(row * 128 + c8 * 16),
             p + (size_t)row * H1D + k0 + c8 * 8);
    }
    CP_COMMIT();
}

__global__ void __launch_bounds__(256, 2)
gemm2_kernel(const float* __restrict__ b2, const float* __restrict__ bg,
             float* __restrict__ out) {
    extern __shared__ char sm[];
    uint32_t smb = smem_u32(sm);
    float* sgate = (float*)(sm + 4 * G2_STAGE);   // [2][64][8]
    const int b0 = blockIdx.x * 64;
    const int tid = threadIdx.x, L = tid & 31, w = tid >> 5;
    const int wm = (w >> 2) * 32, wn = (w & 3) * 32;

    // Prologue: prefetch chunks 0..2.
    gemm2_load(smb, 0, tid, b0, 0);
    gemm2_load(smb, 1, tid, b0, 1);
    gemm2_load(smb, 2, tid, b0, 2);

    // Fused softmax: threads 0..127 each handle one (row, task).
    if (tid < 128) {
        int r = tid >> 1, t = tid & 1;
        int b = b0 + r;
        float4 l0 = *(const float4*)(g_glogits + (size_t)b * 16 + t * 8);
        float4 l1 = *(const float4*)(g_glogits + (size_t)b * 16 + t * 8 + 4);
        float v[8] = {l0.x, l0.y, l0.z, l0.w, l1.x, l1.y, l1.z, l1.w};
        float m = -1e30f;
#pragma unroll
        for (int e2 = 0; e2 < 8; e2++) { v[e2] += bg[t * 8 + e2]; m = fmaxf(m, v[e2]); }
        float s = 0.f;
#pragma unroll
        for (int e2 = 0; e2 < 8; e2++) { v[e2] = expf(v[e2] - m); s += v[e2]; }
        float inv = 1.f / s;
#pragma unroll
        for (int e2 = 0; e2 < 8; e2++)
            sgate[(t * 64 + r) * 8 + e2] = v[e2] * inv;
    }

    float tacc[2][2][4][4];   // [task][mt][nt][quad]
#pragma unroll
    for (int t = 0; t < 2; t++)
#pragma unroll
        for (int mt = 0; mt < 2; mt++)
#pragma unroll
            for (int nt = 0; nt < 4; nt++)
#pragma unroll
                for (int q = 0; q < 4; q++) tacc[t][mt][nt][q] = 0.f;
    float eo[2][4][4];
#pragma unroll
    for (int mt = 0; mt < 2; mt++)
#pragma unroll
        for (int nt = 0; nt < 4; nt++)
#pragma unroll
            for (int q = 0; q < 4; q++) eo[mt][nt][q] = 0.f;

    for (int cg = 0; cg < 32; cg++) {
        CP_WAIT2();
        __syncthreads();
        if (cg + 3 < 32)
            gemm2_load(smb, (cg + 3) & 3, tid, b0, cg + 3);
        else
            CP_COMMIT();
        uint32_t sb = smb + (uint32_t)(cg & 3) * G2_STAGE;
#pragma unroll
        for (int ks = 0; ks < 4; ks++) {
            uint32_t af[2][4], bf[4][2];
#pragma unroll
            for (int mt = 0; mt < 2; mt++) {
                int row = wm + mt * 16 + (L & 15);
                int co = ks * 32 + ((L >> 4) & 1) * 16;
                ldsm4(af[mt], sb + 0u + SWZ(row * 128 + co));
            }
#pragma unroll
            for (int np = 0; np < 2; np++) {
                int g = L >> 3;
                int n = wn + np * 16 + (g >> 1) * 8 + (L & 7);
                int co = ks * 32 + (g & 1) * 16;
                uint32_t r[4];
                ldsm4(r, sb + 8192u + SWZ(n * 128 + co));
                bf[np * 2][0] = r[0]; bf[np * 2][1] = r[1];
                bf[np * 2 + 1][0] = r[2]; bf[np * 2 + 1][1] = r[3];
            }
#pragma unroll
            for (int mt = 0; mt < 2; mt++)
#pragma unroll
                for (int nt = 0; nt < 4; nt++)
                    mma16816(eo[mt][nt], af[mt], bf[nt]);
        }

        if ((cg & 3) == 3) {
            // Expert complete: relu+bias, gate-weight, fold into towers.
            int e = cg >> 2;
#pragma unroll
            for (int mt = 0; mt < 2; mt++) {
                int r1 = wm + mt * 16 + (L >> 2);
                int r2 = r1 + 8;
                float g0a = sgate[(0 * 64 + r1) * 8 + e];
                float g0b = sgate[(0 * 64 + r2) * 8 + e];
                float g1a = sgate[(1 * 64 + r1) * 8 + e];
                float g1b = sgate[(1 * 64 + r2) * 8 + e];
#pragma unroll
                for (int nt = 0; nt < 4; nt++) {
                    int gc = wn + nt * 8 + 2 * (L & 3);
                    float bz0 = b2[e * H2D + gc];
                    float bz1 = b2[e * H2D + gc + 1];
                    float v00 = fmaxf(eo[mt][nt][0] + bz0, 0.f);
                    float v01 = fmaxf(eo[mt][nt][1] + bz1, 0.f);
                    float v10 = fmaxf(eo[mt][nt][2] + bz0, 0.f);
                    float v11 = fmaxf(eo[mt][nt][3] + bz1, 0.f);
                    tacc[0][mt][nt][0] += g0a * v00; tacc[0][mt][nt][1] += g0a * v01;
                    tacc[0][mt][nt][2] += g0b * v10; tacc[0][mt][nt][3] += g0b * v11;
                    tacc[1][mt][nt][0] += g1a * v00; tacc[1][mt][nt][1] += g1a * v01;
                    tacc[1][mt][nt][2] += g1b * v10; tacc[1][mt][nt][3] += g1b * v11;
                    eo[mt][nt][0] = 0.f; eo[mt][nt][1] = 0.f;
                    eo[mt][nt][2] = 0.f; eo[mt][nt][3] = 0.f;
                }
            }
        }
    }

    // Write towers: out[t][b][h2]
#pragma unroll
    for (int t = 0; t < 2; t++)
#pragma unroll
        for (int mt = 0; mt < 2; mt++) {
            int r1 = b0 + wm + mt * 16 + (L >> 2);
#pragma unroll
            for (int nt = 0; nt < 4; nt++) {
                int gc = wn + nt * 8 + 2 * (L & 3);
                *(float2*)(out + ((size_t)t * B_DIM + r1) * H2D + gc) =
                    make_float2(tacc[t][mt][nt][0], tacc[t][mt][nt][1]);
                *(float2*)(out + ((size_t)t * B_DIM + r1 + 8) * H2D + gc) =
                    make_float2(tacc[t][mt][nt][2], tacc[t][mt][nt][3]);
            }
        }
}

// ---------------------------------------------------------------------------
// Unified prep kernel (flat grid, branch on block id):
//   [0, 8192)          conv_x: f32 -> fp16, 4 elems/thread
//   [8192, 9216)       prep_w1: transpose + fp16  (1024 blocks)
//   [9216, 9472)       prep_w2: transpose + fp16  (256 blocks)
//   [9472, 9504)       prep_wg: gather + fp16     (32 blocks)
// ---------------------------------------------------------------------------
#define PREP_BLOCKS 9504

__global__ void prep_kernel(const float* __restrict__ x,
                            const float* __restrict__ W1,
                            const float* __restrict__ W2,
                            const float* __restrict__ Wg) {
    __shared__ float t[32][33];
    int bid = blockIdx.x;
    int tid = threadIdx.x;

    if (bid < 8192) {
        // conv_x
        size_t idx = (size_t)bid * 256 + tid;
        float4 v = ((const float4*)x)[idx];
        __half2 p0, p1;
        p0.x = __float2half_rn(v.x); p0.y = __float2half_rn(v.y);
        p1.x = __float2half_rn(v.z); p1.y = __float2half_rn(v.w);
        ((__half2*)g_x16)[idx * 2 + 0] = p0;
        ((__half2*)g_x16)[idx * 2 + 1] = p1;
    } else if (bid < 9216) {
        // prep_w1: block b2 = bid-8192 over (E=8) x (I/32=16) x (H1/32=8)
        int b2 = bid - 8192;
        int e = b2 >> 7, rem = b2 & 127;
        int i0 = (rem >> 3) * 32, h0 = (rem & 7) * 32;
        int tx = tid & 31, ty = tid >> 5;
        const float* src = W1 + (size_t)e * I_DIM * H1D;
#pragma unroll
        for (int j = 0; j < 4; j++)
            t[ty + j * 8][tx] = src[(size_t)(i0 + ty + j * 8) * H1D + h0 + tx];
        __syncthreads();
#pragma unroll
        for (int j = 0; j < 4; j++) {
            float v = t[tx][ty + j * 8];
            size_t o = ((size_t)e * H1D + h0 + ty + j * 8) * I_DIM + i0 + tx;
            g_w1t[o] = __float2half_rn(v);
        }
    } else if (bid < 9472) {
        // prep_w2: block b2 = bid-9216 over (E=8) x (H1/32=8) x (H2/32=4)
        int b2 = bid - 9216;
        int e = b2 >> 5, rem = b2 & 31;
        int h1_0 = (rem >> 2) * 32, h2_0 = (rem & 3) * 32;
        int tx = tid & 31, ty = tid >> 5;
        const float* src = W2 + (size_t)e * H1D * H2D;
#pragma unroll
        for (int j = 0; j < 4; j++)
            t[ty + j * 8][tx] = src[(size_t)(h1_0 + ty + j * 8) * H2D + h2_0 + tx];
        __syncthreads();
#pragma unroll
        for (int j = 0; j < 4; j++) {
            float v = t[tx][ty + j * 8];
            size_t o = ((size_t)e * H2D + h2_0 + ty + j * 8) * H1D + h1_0 + tx;
            g_w2t[o] = __float2half_rn(v);
        }
    } else {
        // prep_wg
        int idx = (bid - 9472) * 256 + tid;
        int i = idx & (I_DIM - 1), r = idx >> 9;
        int tt = r >> 3, e = r & 7;
        float v = Wg[((size_t)tt * I_DIM + i) * E_DIM + e];
        g_wgt[(size_t)r * I_DIM + i] = __float2half_rn(v);
    }
}

// ---------------------------------------------------------------------------
extern "C" void kernel_launch(void* const* d_in, const int* in_sizes, int n_in,
                              void* d_out, int out_size) {
    const float* x  = (const float*)d_in[0];
    const float* W1 = (const float*)d_in[1];
    const float* b1 = (const float*)d_in[2];
    const float* W2 = (const float*)d_in[3];
    const float* b2 = (const float*)d_in[4];
    const float* Wg = (const float*)d_in[5];
    const float* bg = (const float*)d_in[6];
    float* out = (float*)d_out;

    cudaFuncSetAttribute(gemm1_kernel, cudaFuncAttributeMaxDynamicSharedMemorySize, G1_SMEM);
    cudaFuncSetAttribute(gemm2_kernel, cudaFuncAttributeMaxDynamicSharedMemorySize, G2_SMEM);

    prep_kernel<<<PREP_BLOCKS, 256>>>(x, W1, W2, Wg);
    gemm1_kernel<<<dim3(B_DIM / 128, H1D / 128, E_DIM), 256, G1_SMEM>>>(b1);
    gemm2_kernel<<<B_DIM / 64, 256, G2_SMEM>>>(b2, bg, out);
}